// round 17
// baseline (speedup 1.0000x reference)
#include <cuda_runtime.h>
#include <cuda_fp16.h>
#include <cstdint>

// ---------------------------------------------------------------------------
// Problem constants
// ---------------------------------------------------------------------------
constexpr int B_   = 4;
constexpr int C_   = 256;
constexpr int H_   = 64;
constexpr int W_   = 64;
constexpr int Co_  = 256;
constexpr int HW_  = 64 * 64;           // 4096
constexpr int F_   = C_ * 9;            // 2304  (f' = k*256 + c)
constexpr int N_   = B_ * HW_;          // 16384

// Scratch
__device__ __align__(1024) __half g_xt[(size_t)B_ * HW_ * C_];   // NHWC fp16 8.4MB
__device__ __align__(1024) __half g_wt[(size_t)Co_ * F_];        // fp16 [co][k*256+c]
__device__ __align__(1024) int4   g_idx[(size_t)N_ * 9];         // corner elem offsets
__device__ __align__(1024) float4 g_wgt[(size_t)N_ * 9];         // bilinear weights

// ---------------------------------------------------------------------------
// Helpers
// ---------------------------------------------------------------------------
__device__ __forceinline__ uint32_t smem_u32(const void* p) {
    uint32_t a;
    asm("{ .reg .u64 t; cvta.to.shared.u64 t, %1; cvt.u32.u64 %0, t; }" : "=r"(a) : "l"(p));
    return a;
}
__device__ __forceinline__ void cp_async16(uint32_t dst, const void* src) {
    asm volatile("cp.async.cg.shared.global [%0], [%1], 16;" :: "r"(dst), "l"(src));
}
#define CP_COMMIT() asm volatile("cp.async.commit_group;" ::: "memory")
#define CP_WAIT0()  asm volatile("cp.async.wait_group 0;" ::: "memory")

#define BAR_SYNC(id)   asm volatile("bar.sync %0, %1;"   :: "r"(id), "r"(640) : "memory")
#define BAR_ARRIVE(id) asm volatile("bar.arrive %0, %1;" :: "r"(id), "r"(640) : "memory")

#define LDSM_X4(r0, r1, r2, r3, addr)                                          \
    asm volatile("ldmatrix.sync.aligned.m8n8.x4.shared.b16 {%0,%1,%2,%3}, [%4];" \
                 : "=r"(r0), "=r"(r1), "=r"(r2), "=r"(r3) : "r"(addr))

#define MMA_F16(d, a, b0, b1)                                                  \
    asm volatile("mma.sync.aligned.m16n8k16.row.col.f32.f16.f16.f32 "          \
                 "{%0,%1,%2,%3},{%4,%5,%6,%7},{%8,%9},{%0,%1,%2,%3};"          \
                 : "+f"((d)[0]), "+f"((d)[1]), "+f"((d)[2]), "+f"((d)[3])      \
                 : "r"((a)[0]), "r"((a)[1]), "r"((a)[2]), "r"((a)[3]),         \
                   "r"(b0), "r"(b1))

// ---------------------------------------------------------------------------
// Kernel 1: x NCHW (f32) -> NHWC (fp16)
// ---------------------------------------------------------------------------
__global__ __launch_bounds__(256) void transpose_x(const float* __restrict__ x,
                                                   __half* __restrict__ xt) {
    __shared__ float t[32][33];
    int b = blockIdx.z, c0 = blockIdx.y * 32, l0 = blockIdx.x * 32;
    int tx = threadIdx.x & 31, ty = threadIdx.x >> 5;
    const float* xb = x + ((size_t)b * C_ + c0) * HW_;
    #pragma unroll
    for (int j = 0; j < 32; j += 8)
        t[ty + j][tx] = xb[(size_t)(ty + j) * HW_ + l0 + tx];
    __syncthreads();
    __half* xo = xt + ((size_t)b * HW_ + l0) * C_;
    #pragma unroll
    for (int j = 0; j < 32; j += 8)
        xo[(size_t)(ty + j) * C_ + c0 + tx] = __float2half_rn(t[tx][ty + j]);
}

// ---------------------------------------------------------------------------
// Kernel 2: weight [co][c][k] -> W_t [co][k*256+c], fp16
// ---------------------------------------------------------------------------
__global__ __launch_bounds__(256) void transpose_w(const float* __restrict__ w,
                                                   __half* __restrict__ wt) {
    int co = blockIdx.x;
    const float* wi = w + (size_t)co * F_;
    __half* wo = wt + (size_t)co * F_;
    for (int i = threadIdx.x; i < F_; i += 256) {
        int c = i / 9, kk = i % 9;
        wo[kk * 256 + c] = __float2half_rn(wi[i]);
    }
}

// ---------------------------------------------------------------------------
// Kernel 3: precompute bilinear corner offsets and weights per (n, k)
// ---------------------------------------------------------------------------
__global__ __launch_bounds__(256) void prep_off(const float* __restrict__ off,
                                                int4* __restrict__ gidx,
                                                float4* __restrict__ gwgt) {
    int g = blockIdx.x * 256 + threadIdx.x;     // n*9 + k
    if (g >= N_ * 9) return;
    int n = g / 9, k = g - n * 9;
    int b = n >> 12, p = n & 4095;
    int ho = p >> 6, wo = p & 63;
    int ki = k / 3, kj = k - ki * 3;

    float sy = off[((size_t)(b * 18 + 2 * k))     * HW_ + p] + (float)(ho - 1 + ki);
    float sx = off[((size_t)(b * 18 + 2 * k + 1)) * HW_ + p] + (float)(wo - 1 + kj);

    float y0f = floorf(sy), x0f = floorf(sx);
    float dy = sy - y0f, dx = sx - x0f;
    int y0 = (int)y0f, x0 = (int)x0f, y1 = y0 + 1, x1 = x0 + 1;
    bool vy0 = (y0 >= 0) & (y0 < H_), vy1 = (y1 >= 0) & (y1 < H_);
    bool vx0 = (x0 >= 0) & (x0 < W_), vx1 = (x1 >= 0) & (x1 < W_);

    float4 wv;
    wv.x = (1.f - dy) * (1.f - dx) * (float)(vy0 && vx0);
    wv.y = (1.f - dy) * dx         * (float)(vy0 && vx1);
    wv.z = dy * (1.f - dx)         * (float)(vy1 && vx0);
    wv.w = dy * dx                 * (float)(vy1 && vx1);

    int y0c = min(max(y0, 0), H_ - 1), y1c = min(max(y1, 0), H_ - 1);
    int x0c = min(max(x0, 0), W_ - 1), x1c = min(max(x1, 0), W_ - 1);
    int base = b * HW_;
    int4 iv;
    iv.x = (base + y0c * W_ + x0c) * C_;
    iv.y = (base + y0c * W_ + x1c) * C_;
    iv.z = (base + y1c * W_ + x0c) * C_;
    iv.w = (base + y1c * W_ + x1c) * C_;

    gidx[g] = iv;
    gwgt[g] = wv;
}

// ---------------------------------------------------------------------------
// Kernel 4: warp-specialized fused im2col + FP16 GEMM (m16n8k16, fp32 acc).
// 640 threads: warps 0-15 consumers (4x4 grid, 64x32 warp tile, 64-reg acc);
// warps 16-19 producers (cp.async A + fp16 bilinear gather -> STS B).
// KCH=64, 3-stage ring (48KB) + 36KB smem tables. CHUNKS=36.
// Named barriers (count 640): full[s] = 1+s, empty[s] = 4+s.
// ---------------------------------------------------------------------------
constexpr int KCH    = 64;                 // fp16 k-elements per chunk
constexpr int CHUNKS = F_ / KCH;           // 36
constexpr int A_STG  = 256 * 128;          // 32KB (256 rows x 128B)
constexpr int B_OFF  = A_STG;
constexpr int STG_SZ = A_STG + 128 * 128;  // 48KB
constexpr int STAGES = 3;
constexpr int TBL_OFF = STAGES * STG_SZ;        // 144KB
constexpr int GEMM_SMEM = TBL_OFF + 128 * 9 * 32;   // +36KB = 180KB

__global__ __launch_bounds__(640, 1) void gemm_ws(const __half* __restrict__ Wt,
                                                  const __half* __restrict__ xt,
                                                  const int4* __restrict__ gidx,
                                                  const float4* __restrict__ gwgt,
                                                  float* __restrict__ out) {
    extern __shared__ char smem[];
    uint32_t sb = smem_u32(smem);
    int tid = threadIdx.x, lane = tid & 31;
    int n0 = blockIdx.x * 128;

    // Cooperative table load: 128 rows x 9 taps, 32B each (iv, wv).
    for (int e = tid; e < 128 * 9; e += 640) {
        int gi = n0 * 9 + e;
        *(int4*)(smem + TBL_OFF + e * 32)        = gidx[gi];
        *(float4*)(smem + TBL_OFF + e * 32 + 16) = gwgt[gi];
    }
    __syncthreads();

    if (tid < 512) {
        // ============ CONSUMERS: 16 warps, 4x4 grid, 64x32 tiles ============
        int warp = tid >> 5;
        int wm = warp & 3, wn = warp >> 2;
        int sel = lane >> 3, row_in = lane & 7;

        // Compressed fragment addressing (m&7 == row_in, f-independent XOR).
        uint32_t abase = (uint32_t)(wm * 8192 + ((sel & 1) * 8 + row_in) * 128);
        uint32_t ax    = (uint32_t)((row_in << 4) ^ ((sel >> 1) << 4));
        uint32_t bbase = (uint32_t)(B_OFF + wn * 4096 +
                                    ((sel >> 1) * 8 + row_in) * 128);
        uint32_t bx    = (uint32_t)((row_in << 4) ^ ((sel & 1) << 4));

        float acc[4][4][4];
        #pragma unroll
        for (int f = 0; f < 4; f++)
            #pragma unroll
            for (int j = 0; j < 4; j++)
                #pragma unroll
                for (int q = 0; q < 4; q++) acc[f][j][q] = 0.f;

        int s = 0;
        for (int i = 0; i < CHUNKS; i++) {
            uint32_t slot = sb + s * STG_SZ;
            BAR_SYNC(1 + s);                      // wait full[s] (A+B ready)

            #pragma unroll
            for (int ks = 0; ks < 4; ks++) {      // k16 per iteration
                uint32_t kb = ks * 32;            // 32B = 16 fp16
                uint32_t kxa = kb ^ ax, kxb = kb ^ bx;
                uint32_t a[4][4], bb[2][4];
                #pragma unroll
                for (int f = 0; f < 4; f++)
                    LDSM_X4(a[f][0], a[f][1], a[f][2], a[f][3],
                            slot + abase + f * 2048 + kxa);
                #pragma unroll
                for (int g = 0; g < 2; g++)
                    LDSM_X4(bb[g][0], bb[g][1], bb[g][2], bb[g][3],
                            slot + bbase + g * 2048 + kxb);
                #pragma unroll
                for (int f = 0; f < 4; f++)
                    #pragma unroll
                    for (int j2 = 0; j2 < 4; j2++)
                        MMA_F16(acc[f][j2], a[f],
                                bb[j2 >> 1][(j2 & 1) * 2], bb[j2 >> 1][(j2 & 1) * 2 + 1]);
            }
            BAR_ARRIVE(4 + s);                    // signal empty[s]
            s = (s == 2) ? 0 : s + 1;
        }

        // Epilogue
        int tig = lane & 3, gid = lane >> 2;
        int b = n0 >> 12;
        int pbase = (n0 & 4095) + wn * 32;
        #pragma unroll
        for (int f = 0; f < 4; f++) {
            #pragma unroll
            for (int j = 0; j < 4; j++) {
                int co = wm * 64 + f * 16 + gid;
                int p  = pbase + j * 8 + tig * 2;
                float* o0 = out + ((size_t)(b * Co_ + co)) * HW_ + p;
                *(float2*)o0 = make_float2(acc[f][j][0], acc[f][j][1]);
                *(float2*)(o0 + (size_t)8 * HW_) = make_float2(acc[f][j][2], acc[f][j][3]);
            }
        }
    } else {
        // ========== PRODUCERS (4 warps, 128 threads): A + B gather ==========
        int pt   = tid - 512;                     // 0..127
        int prow = pt >> 3;                       // 0..15
        int pc16 = pt & 7;                        // 0..7  (8 fp16 channels each)

        int s = 0;
        for (int kk = 0; kk < 9; kk++) {
            for (int cc = 0; cc < 4; cc++) {
                int i = kk * 4 + cc;
                if (i >= STAGES) BAR_SYNC(4 + s); // wait empty[s]

                // A: 256 rows x 128B via cp.async (16 per thread)
                uint32_t aslot = sb + s * STG_SZ;
                int kg = i * KCH;
                #pragma unroll
                for (int it = 0; it < 16; it++) {
                    int u = pt + it * 128;
                    int row = u >> 3, c16 = u & 7;
                    cp_async16(aslot + row * 128 + ((c16 * 16) ^ ((row & 7) << 4)),
                               Wt + (size_t)row * F_ + kg + c16 * 8);
                }
                CP_COMMIT();

                // B gather: 8 outputs/thread in 2 batches of 4 rows.
                // Rows: prow + b2*16 + j*32  -> {prow, prow+16} + {0,32,64,96}
                // Union over prow 0..15 and b2 = all 128 rows exactly once.
                int cb = cc * 64 + pc16 * 8;      // fp16 channel base
                char* bslot = smem + s * STG_SZ + B_OFF;
                uint32_t sxor = (uint32_t)((pc16 * 16) ^ ((prow & 7) << 4));
                #pragma unroll
                for (int b2 = 0; b2 < 2; b2++) {
                    uint4 v[4][4];
                    #pragma unroll
                    for (int j = 0; j < 4; j++) {
                        int row = prow + b2 * 16 + j * 32;
                        int4 iv = *(const int4*)(smem + TBL_OFF +
                                                 (row * 9 + kk) * 32);
                        v[j][0] = *(const uint4*)(xt + iv.x + cb);
                        v[j][1] = *(const uint4*)(xt + iv.y + cb);
                        v[j][2] = *(const uint4*)(xt + iv.z + cb);
                        v[j][3] = *(const uint4*)(xt + iv.w + cb);
                    }
                    #pragma unroll
                    for (int j = 0; j < 4; j++) {
                        int row = prow + b2 * 16 + j * 32;
                        float4 wv = *(const float4*)(smem + TBL_OFF +
                                                     (row * 9 + kk) * 32 + 16);
                        const __half2* h00 = (const __half2*)&v[j][0];
                        const __half2* h01 = (const __half2*)&v[j][1];
                        const __half2* h10 = (const __half2*)&v[j][2];
                        const __half2* h11 = (const __half2*)&v[j][3];
                        uint4 pk;
                        uint32_t* pko = (uint32_t*)&pk;
                        #pragma unroll
                        for (int g = 0; g < 4; g++) {
                            float2 a0 = __half22float2(h00[g]);
                            float2 a1 = __half22float2(h01[g]);
                            float2 a2 = __half22float2(h10[g]);
                            float2 a3 = __half22float2(h11[g]);
                            float rx = wv.x*a0.x + wv.y*a1.x + wv.z*a2.x + wv.w*a3.x;
                            float ry = wv.x*a0.y + wv.y*a1.y + wv.z*a2.y + wv.w*a3.y;
                            __half2 h = __floats2half2_rn(rx, ry);
                            pko[g] = *(uint32_t*)&h;
                        }
                        *(uint4*)(bslot + row * 128 + sxor) = pk;
                    }
                }

                CP_WAIT0();                       // A landed
                BAR_ARRIVE(1 + s);                // signal full[s]
                s = (s == 2) ? 0 : s + 1;
            }
        }
    }
}

// ---------------------------------------------------------------------------
extern "C" void kernel_launch(void* const* d_in, const int* in_sizes, int n_in,
                              void* d_out, int out_size) {
    const float* x      = (const float*)d_in[0];
    const float* offset = (const float*)d_in[1];
    const float* weight = (const float*)d_in[2];
    float* out = (float*)d_out;

    __half *xt, *wt;
    int4* gidx;
    float4* gwgt;
    cudaGetSymbolAddress((void**)&xt, g_xt);
    cudaGetSymbolAddress((void**)&wt, g_wt);
    cudaGetSymbolAddress((void**)&gidx, g_idx);
    cudaGetSymbolAddress((void**)&gwgt, g_wgt);

    cudaFuncSetAttribute(gemm_ws, cudaFuncAttributeMaxDynamicSharedMemorySize, GEMM_SMEM);

    {
        dim3 grid(HW_ / 32, C_ / 32, B_);
        transpose_x<<<grid, 256>>>(x, xt);
    }
    transpose_w<<<Co_, 256>>>(weight, wt);
    prep_off<<<(N_ * 9 + 255) / 256, 256>>>(offset, gidx, gwgt);
    gemm_ws<<<N_ / 128, 640, GEMM_SMEM>>>(wt, xt, gidx, gwgt, out);
}